// round 14
// baseline (speedup 1.0000x reference)
#include <cuda_runtime.h>
#include <math.h>

#define EPSV 1e-5f
#define VFLOOR 1e-6f

// Fixed shape: B=4, L=4096, D=2048, G=16 (gs=128).
constexpr int Lc  = 4096;
constexpr int Gc  = 16;
constexpr int Dc  = 2048;
constexpr int CH  = 8;
constexpr int NCH = Lc / CH;      // 512
constexpr int MAXB = 8;

__device__ float  g_gmT [MAXB * Gc * Lc];   // (b,g,l) group means
__device__ float2 g_stat[MAXB * Gc * Lc];   // (b,g,l) {mean, rstd}

// ---------------------------------------------------------------------------
// K1: group means only. Block = 8-row chunk; warp g reduces group g per row.
// __ldcg: allocate in L2 (for K3's reversed re-read) but skip L1 (no reuse).
// ---------------------------------------------------------------------------
__global__ void __launch_bounds__(512)
k_gm(const float* __restrict__ x)
{
    const unsigned FULL = 0xffffffffu;
    const int b    = blockIdx.x >> 9;
    const int ch   = blockIdx.x & (NCH - 1);
    const int lane = threadIdx.x & 31;
    const int g    = threadIdx.x >> 5;
    const int rowBase = b * Lc + ch * CH;

    const float4* xr = (const float4*)x;
    float4 v[CH];
    #pragma unroll
    for (int r = 0; r < CH; r++)
        v[r] = __ldcg(&xr[(size_t)(rowBase + r) * (Dc / 4) + g * 32 + lane]);

    float mygm = 0.0f;
    #pragma unroll
    for (int r = 0; r < CH; r++) {
        float s = (v[r].x + v[r].y) + (v[r].z + v[r].w);
        #pragma unroll
        for (int o = 16; o > 0; o >>= 1)
            s += __shfl_xor_sync(FULL, s, o);
        if (lane == r) mygm = s * (1.0f / 128.0f);
    }
    if (lane < CH)
        g_gmT[(b * Gc + g) * Lc + ch * CH + lane] = mygm;
}

// ---------------------------------------------------------------------------
// K2: per-(b,g) scan over L using the Chan closed form (validated R7/R12):
// one hierarchical scan of (S, Q, C), then mean/var directly per element.
// 64 blocks, 512 threads, 8 elems/thread. Emits (mean,rstd) float2 + tail.
// ---------------------------------------------------------------------------
__global__ void __launch_bounds__(512)
k_scan(const int* __restrict__ prev_count,
       const float* __restrict__ prev_mean,
       const float* __restrict__ prev_var,
       const int* __restrict__ pmask,
       float* __restrict__ outF,
       int B, int writeTail, long long tailOff)
{
    constexpr int P = 8;
    const int b = blockIdx.x / Gc;
    const int g = blockIdx.x - b * Gc;
    const int tid  = threadIdx.x;
    const int lane = tid & 31;
    const int wid  = tid >> 5;
    const unsigned FULL = 0xffffffffu;

    const float pc     = (float)prev_count[b];
    const float pmeanv = prev_mean[b * Gc + g];
    const float pvarv  = prev_var[b * Gc + g];
    const float psum   = pmeanv * pc;
    const float pm2    = pvarv * fmaxf(pc, 1.0f);

    __shared__ float smS[16], smQ[16], smC[16];

    const float* gmrow = &g_gmT[(b * Gc + g) * Lc];

    // thread-local inclusive scan of (gm*v, gm^2*v, v)
    float ls[P], lq[P], lc[P];
    float sa = 0.f, qa = 0.f, ca = 0.f;
    #pragma unroll
    for (int j = 0; j < P; j++) {
        const int l = tid * P + j;
        const float gmv = gmrow[l];
        const float vd  = pmask[b * Lc + l] ? 1.0f : 0.0f;
        sa += gmv * vd;
        qa += gmv * gmv * vd;
        ca += vd;
        ls[j] = sa; lq[j] = qa; lc[j] = ca;
    }

    // warp inclusive scan of thread totals
    float ws = sa, wq = qa, wc = ca;
    #pragma unroll
    for (int o = 1; o < 32; o <<= 1) {
        const float ns = __shfl_up_sync(FULL, ws, o);
        const float nq = __shfl_up_sync(FULL, wq, o);
        const float nc = __shfl_up_sync(FULL, wc, o);
        if (lane >= o) { ws += ns; wq += nq; wc += nc; }
    }
    const float exs = ws - sa, exq = wq - qa, exc = wc - ca;

    if (lane == 31) { smS[wid] = ws; smQ[wid] = wq; smC[wid] = wc; }
    __syncthreads();
    if (tid == 0) {
        float rs = 0.f, rq = 0.f, rc = 0.f;
        #pragma unroll
        for (int i = 0; i < 16; i++) {
            const float ts = smS[i], tq = smQ[i], tc = smC[i];
            smS[i] = rs; smQ[i] = rq; smC[i] = rc;
            rs += ts; rq += tq; rc += tc;
        }
    }
    __syncthreads();
    const float baseS = smS[wid] + exs;
    const float baseQ = smQ[wid] + exq;
    const float baseC = smC[wid] + exc;

    float2* statrow = &g_stat[(size_t)(b * Gc + g) * Lc];
    #pragma unroll
    for (int j = 0; j < P; j++) {
        const int l = tid * P + j;
        const float S = baseS + ls[j];
        const float Q = baseQ + lq[j];
        const float C = baseC + lc[j];
        const float count_t = pc + C;

        float mean_t = pmeanv, var = pvarv;
        if (count_t > 0.0f) {
            mean_t = (psum + S) / fmaxf(count_t, 1.0f);
            float sumdd = 0.0f;
            if (C > 0.0f) {
                const float bm  = S / C;
                const float m2b = Q - bm * S;
                const float dlt = bm - pmeanv;
                sumdd = m2b + dlt * dlt * (pc * C / (pc + C));
            }
            var = (pm2 + sumdd) / fmaxf(count_t, 1.0f);
        }
        var = fmaxf(var, VFLOOR);
        statrow[l] = make_float2(mean_t, rsqrtf(var + EPSV));
        if (writeTail && l == Lc - 1) {
            outF[tailOff + B + b * Gc + g]                  = mean_t;
            outF[tailOff + B + (size_t)B * Gc + b * Gc + g] = var;
            if (g == 0) outF[tailOff + b] = count_t;
        }
    }
}

// ---------------------------------------------------------------------------
// K3: elementwise normalize, block = exactly 8 rows (64 KB), REVERSED block
// order (first wave reads the tail of x, still L2-resident from K1).
// Stats staged once through smem (1 KB per block) -> hot loop has zero L2
// stat traffic and trivial index math: row = k, group = warpid.
// x read evict-first (__ldcs); y written evict-first (__stcs).
// ---------------------------------------------------------------------------
__global__ void __launch_bounds__(512)
k_norm(const float* __restrict__ x,
       const float* __restrict__ wgt,
       const float* __restrict__ bias,
       float* __restrict__ outF)
{
    constexpr int NR = 8;                       // rows per block
    const int tid  = threadIdx.x;
    const int g    = tid >> 5;                  // warp = group
    const int rbid = gridDim.x - 1 - blockIdx.x;
    const int rowBase = rbid * NR;              // global row (b*Lc + l)

    __shared__ float2 smst[NR][Gc];

    // stage this block's 8x16 stats (128 float2) cooperatively
    if (tid < NR * Gc) {
        const int r  = tid >> 4;
        const int gi = tid & 15;
        const int row = rowBase + r;
        const int b   = row >> 12;
        const int l   = row & (Lc - 1);
        smst[r][gi] = g_stat[((size_t)(b * Gc + gi)) * Lc + l];
    }

    float4 wv = ((const float4*)wgt)[tid];
    float4 bv = ((const float4*)bias)[tid];
    wv.x += 1.f; wv.y += 1.f; wv.z += 1.f; wv.w += 1.f;
    __syncthreads();

    const float4* xr = (const float4*)x;
    float4* yr = (float4*)outF;
    const size_t base = (size_t)rowBase * (Dc / 4) + tid;

    #pragma unroll
    for (int k = 0; k < NR; k++) {
        const size_t idx = base + (size_t)k * 512;
        const float4 v = __ldcs(&xr[idx]);
        const float2 st = smst[k][g];
        const float mn = st.x, rs = st.y;
        float4 o;
        o.x = (v.x - mn) * rs * wv.x + bv.x;
        o.y = (v.y - mn) * rs * wv.y + bv.y;
        o.z = (v.z - mn) * rs * wv.z + bv.z;
        o.w = (v.w - mn) * rs * wv.w + bv.w;
        __stcs(&yr[idx], o);
    }
}

// ---------------------------------------------------------------------------
extern "C" void kernel_launch(void* const* d_in, const int* in_sizes, int n_in,
                              void* d_out, int out_size)
{
    const float* x     = (const float*)d_in[0];
    const int*   pcnt  = (const int*)d_in[1];
    const float* pmean = (const float*)d_in[2];
    const float* pvar  = (const float*)d_in[3];
    const int*   pmask = (const int*)d_in[4];
    const float* wgt   = (const float*)d_in[5];
    const float* bias  = (const float*)d_in[6];
    float*       outF  = (float*)d_out;

    const int B = in_sizes[1];
    const int G = in_sizes[2] / B;     // 16
    const int D = in_sizes[5];         // 2048
    const int L = in_sizes[4] / B;     // 4096
    (void)G; (void)D; (void)L;

    const long long BLD = (long long)B * L * D;
    const long long expected = BLD + B + 2LL * B * G;
    const int writeTail = (out_size >= expected) ? 1 : 0;

    k_gm  <<<B * NCH, 512>>>(x);
    k_scan<<<B * Gc, 512>>>(pcnt, pmean, pvar, pmask, outF, B, writeTail, BLD);

    const int blocks = B * Lc / 8;                // 2048 blocks, 8 rows each
    k_norm<<<blocks, 512>>>(x, wgt, bias, outF);
}

// round 15
// speedup vs baseline: 1.0265x; 1.0265x over previous
#include <cuda_runtime.h>
#include <math.h>

#define EPSV 1e-5f
#define VFLOOR 1e-6f

// Fixed shape: B=4, L=4096, D=2048, G=16 (gs=128).
constexpr int Lc  = 4096;
constexpr int Gc  = 16;
constexpr int Dc  = 2048;
constexpr int CH  = 8;
constexpr int NCH = Lc / CH;      // 512
constexpr int MAXB = 8;

__device__ float  g_gmT [MAXB * Gc * Lc];   // (b,g,l) group means
__device__ float2 g_stat[MAXB * Gc * Lc];   // (b,g,l) {mean, rstd}

// ---------------------------------------------------------------------------
// K1: group means only. Block = 8-row chunk; warp g reduces group g per row.
// __ldcg: allocate in L2 (for K3's reversed re-read) but skip L1 (no reuse).
// ---------------------------------------------------------------------------
__global__ void __launch_bounds__(512)
k_gm(const float* __restrict__ x)
{
    const unsigned FULL = 0xffffffffu;
    const int b    = blockIdx.x >> 9;
    const int ch   = blockIdx.x & (NCH - 1);
    const int lane = threadIdx.x & 31;
    const int g    = threadIdx.x >> 5;
    const int rowBase = b * Lc + ch * CH;

    const float4* xr = (const float4*)x;
    float4 v[CH];
    #pragma unroll
    for (int r = 0; r < CH; r++)
        v[r] = __ldcg(&xr[(size_t)(rowBase + r) * (Dc / 4) + g * 32 + lane]);

    float mygm = 0.0f;
    #pragma unroll
    for (int r = 0; r < CH; r++) {
        float s = (v[r].x + v[r].y) + (v[r].z + v[r].w);
        #pragma unroll
        for (int o = 16; o > 0; o >>= 1)
            s += __shfl_xor_sync(FULL, s, o);
        if (lane == r) mygm = s * (1.0f / 128.0f);
    }
    if (lane < CH)
        g_gmT[(b * Gc + g) * Lc + ch * CH + lane] = mygm;
}

// ---------------------------------------------------------------------------
// K2: per-(b,g) scan over L using the Chan closed form (validated R7/R12):
// one hierarchical scan of (S, Q, C), then mean/var directly per element.
// 64 blocks, 512 threads, 8 elems/thread. Emits (mean,rstd) float2 + tail.
// ---------------------------------------------------------------------------
__global__ void __launch_bounds__(512)
k_scan(const int* __restrict__ prev_count,
       const float* __restrict__ prev_mean,
       const float* __restrict__ prev_var,
       const int* __restrict__ pmask,
       float* __restrict__ outF,
       int B, int writeTail, long long tailOff)
{
    constexpr int P = 8;
    const int b = blockIdx.x / Gc;
    const int g = blockIdx.x - b * Gc;
    const int tid  = threadIdx.x;
    const int lane = tid & 31;
    const int wid  = tid >> 5;
    const unsigned FULL = 0xffffffffu;

    const float pc     = (float)prev_count[b];
    const float pmeanv = prev_mean[b * Gc + g];
    const float pvarv  = prev_var[b * Gc + g];
    const float psum   = pmeanv * pc;
    const float pm2    = pvarv * fmaxf(pc, 1.0f);

    __shared__ float smS[16], smQ[16], smC[16];

    const float* gmrow = &g_gmT[(b * Gc + g) * Lc];

    // thread-local inclusive scan of (gm*v, gm^2*v, v)
    float ls[P], lq[P], lc[P];
    float sa = 0.f, qa = 0.f, ca = 0.f;
    #pragma unroll
    for (int j = 0; j < P; j++) {
        const int l = tid * P + j;
        const float gmv = gmrow[l];
        const float vd  = pmask[b * Lc + l] ? 1.0f : 0.0f;
        sa += gmv * vd;
        qa += gmv * gmv * vd;
        ca += vd;
        ls[j] = sa; lq[j] = qa; lc[j] = ca;
    }

    // warp inclusive scan of thread totals
    float ws = sa, wq = qa, wc = ca;
    #pragma unroll
    for (int o = 1; o < 32; o <<= 1) {
        const float ns = __shfl_up_sync(FULL, ws, o);
        const float nq = __shfl_up_sync(FULL, wq, o);
        const float nc = __shfl_up_sync(FULL, wc, o);
        if (lane >= o) { ws += ns; wq += nq; wc += nc; }
    }
    const float exs = ws - sa, exq = wq - qa, exc = wc - ca;

    if (lane == 31) { smS[wid] = ws; smQ[wid] = wq; smC[wid] = wc; }
    __syncthreads();
    if (tid == 0) {
        float rs = 0.f, rq = 0.f, rc = 0.f;
        #pragma unroll
        for (int i = 0; i < 16; i++) {
            const float ts = smS[i], tq = smQ[i], tc = smC[i];
            smS[i] = rs; smQ[i] = rq; smC[i] = rc;
            rs += ts; rq += tq; rc += tc;
        }
    }
    __syncthreads();
    const float baseS = smS[wid] + exs;
    const float baseQ = smQ[wid] + exq;
    const float baseC = smC[wid] + exc;

    float2* statrow = &g_stat[(size_t)(b * Gc + g) * Lc];
    #pragma unroll
    for (int j = 0; j < P; j++) {
        const int l = tid * P + j;
        const float S = baseS + ls[j];
        const float Q = baseQ + lq[j];
        const float C = baseC + lc[j];
        const float count_t = pc + C;

        float mean_t = pmeanv, var = pvarv;
        if (count_t > 0.0f) {
            mean_t = (psum + S) / fmaxf(count_t, 1.0f);
            float sumdd = 0.0f;
            if (C > 0.0f) {
                const float bm  = S / C;
                const float m2b = Q - bm * S;
                const float dlt = bm - pmeanv;
                sumdd = m2b + dlt * dlt * (pc * C / (pc + C));
            }
            var = (pm2 + sumdd) / fmaxf(count_t, 1.0f);
        }
        var = fmaxf(var, VFLOOR);
        statrow[l] = make_float2(mean_t, rsqrtf(var + EPSV));
        if (writeTail && l == Lc - 1) {
            outF[tailOff + B + b * Gc + g]                  = mean_t;
            outF[tailOff + B + (size_t)B * Gc + b * Gc + g] = var;
            if (g == 0) outF[tailOff + b] = count_t;
        }
    }
}

// ---------------------------------------------------------------------------
// K3: pure elementwise normalize (R13 shape), REVERSED block order (first
// wave reads the tail of x, still L2-resident from K1). NV=8 per thread as
// two pipelined groups of 4 (keeps live regs at the NV=4 level while halving
// block count and amortizing wgt/bias loads). x read evict-first (__ldcs);
// y written evict-first (__stcs).
// ---------------------------------------------------------------------------
__global__ void __launch_bounds__(512)
k_norm(const float* __restrict__ x,
       const float* __restrict__ wgt,
       const float* __restrict__ bias,
       float* __restrict__ outF)
{
    constexpr int NV = 8;                        // 2 groups of 4
    const int tid = threadIdx.x;
    const int rbid = gridDim.x - 1 - blockIdx.x;          // reversed order
    const long long base = (long long)rbid * (512 * NV) + tid;

    const int d4 = (int)(base & 511);            // invariant across k (stride 512)
    float4 wv = ((const float4*)wgt)[d4];
    float4 bv = ((const float4*)bias)[d4];
    wv.x += 1.f; wv.y += 1.f; wv.z += 1.f; wv.w += 1.f;

    const float4* xr = (const float4*)x;
    float4* yr = (float4*)outF;

    #pragma unroll
    for (int h = 0; h < 2; h++) {
        const long long idx0 = base + (long long)h * 4 * 512;
        float4 v[4];
        float2 st[4];
        #pragma unroll
        for (int k = 0; k < 4; k++) {
            const long long idx = idx0 + (long long)k * 512;
            v[k] = __ldcs(&xr[idx]);
            const int row = (int)(idx >> 9);     // b*Lc + l
            const int g   = ((int)idx >> 5) & 15;
            const int b   = row >> 12;
            const int l   = row & (Lc - 1);
            st[k] = g_stat[((size_t)(b * Gc + g)) * Lc + l];
        }
        #pragma unroll
        for (int k = 0; k < 4; k++) {
            const long long idx = idx0 + (long long)k * 512;
            const float mn = st[k].x, rs = st[k].y;
            float4 o;
            o.x = (v[k].x - mn) * rs * wv.x + bv.x;
            o.y = (v[k].y - mn) * rs * wv.y + bv.y;
            o.z = (v[k].z - mn) * rs * wv.z + bv.z;
            o.w = (v[k].w - mn) * rs * wv.w + bv.w;
            __stcs(&yr[idx], o);
        }
    }
}

// ---------------------------------------------------------------------------
extern "C" void kernel_launch(void* const* d_in, const int* in_sizes, int n_in,
                              void* d_out, int out_size)
{
    const float* x     = (const float*)d_in[0];
    const int*   pcnt  = (const int*)d_in[1];
    const float* pmean = (const float*)d_in[2];
    const float* pvar  = (const float*)d_in[3];
    const int*   pmask = (const int*)d_in[4];
    const float* wgt   = (const float*)d_in[5];
    const float* bias  = (const float*)d_in[6];
    float*       outF  = (float*)d_out;

    const int B = in_sizes[1];
    const int G = in_sizes[2] / B;     // 16
    const int D = in_sizes[5];         // 2048
    const int L = in_sizes[4] / B;     // 4096
    (void)G; (void)D; (void)L;

    const long long BLD = (long long)B * L * D;
    const long long expected = BLD + B + 2LL * B * G;
    const int writeTail = (out_size >= expected) ? 1 : 0;

    k_gm  <<<B * NCH, 512>>>(x);
    k_scan<<<B * Gc, 512>>>(pcnt, pmean, pvar, pmask, outF, B, writeTail, BLD);

    const long long n4 = BLD / 4;                 // 8M float4
    const int blocks = (int)(n4 / (512 * 8));     // 2048
    k_norm<<<blocks, 512>>>(x, wgt, bias, outF);
}